// round 8
// baseline (speedup 1.0000x reference)
#include <cuda_runtime.h>

#define T_LEN 32768
#define D_IN  512
#define HID   20
#define G4    80   // 4*HID

// Scratch (static device arrays; no allocation)
// g_xgp: [t][128], col = lane*4 + slot. Lane l<20: slots {i_l,f_l,g_l,pad}.
// Lane l>=20: slots {o_{l-20}, o_{l-12}, 0, pad}. sigma-gates prescaled x0.5.
__device__ float g_xgp[(size_t)T_LEN * 128];
// g_hT: transposed hidden states [lane][t] (32 rows; only 0..19 meaningful)
__device__ float g_hT[(size_t)32 * T_LEN];

typedef unsigned long long ull;

__device__ __forceinline__ ull pack2(float lo, float hi) {
    ull r;
    asm("mov.b64 %0, {%1, %2};" : "=l"(r) : "f"(lo), "f"(hi));
    return r;
}
__device__ __forceinline__ void unpack2(ull v, float& lo, float& hi) {
    asm("mov.b64 {%0, %1}, %2;" : "=f"(lo), "=f"(hi) : "l"(v));
}
__device__ __forceinline__ void ffma2(ull& acc, ull a, ull b) {
    asm("fma.rn.f32x2 %0, %1, %2, %0;" : "+l"(acc) : "l"(a), "l"(b));
}
__device__ __forceinline__ ull fadd2(ull a, ull b) {
    ull r;
    asm("add.rn.f32x2 %0, %1, %2;" : "=l"(r) : "l"(a), "l"(b));
    return r;
}
__device__ __forceinline__ ull mul2(ull a, ull b) {
    ull r;
    asm("mul.rn.f32x2 %0, %1, %2;" : "=l"(r) : "l"(a), "l"(b));
    return r;
}
__device__ __forceinline__ float tanh_mufu(float x) {
    float r;
    asm("tanh.approx.f32 %0, %1;" : "=f"(r) : "f"(x));
    return r;
}

// ---------------------------------------------------------------------------
// Kernel A: gemm + scatter into the per-lane packed layout. (unchanged)
// ---------------------------------------------------------------------------
__global__ void gemm_xg_kernel(const float* __restrict__ x,
                               const float* __restrict__ W_ih,
                               const float* __restrict__ b_ih,
                               const float* __restrict__ b_hh) {
    __shared__ float xs[64][64];
    __shared__ float ws[80][65];

    const int tid = threadIdx.x;
    const int t0  = blockIdx.x * 64;
    const int rg  = tid >> 4;
    const int gg  = tid & 15;

    // zero unused columns: pad col lane*4+3 (32) + upper-lane slot2 (12)
    for (int idx = tid; idx < 64 * 44; idx += 256) {
        int row = idx / 44;
        int k   = idx % 44;
        int col = (k < 32) ? (k * 4 + 3) : ((20 + (k - 32)) * 4 + 2);
        g_xgp[(size_t)(t0 + row) * 128 + col] = 0.f;
    }

    float acc[4][5];
#pragma unroll
    for (int r = 0; r < 4; ++r)
#pragma unroll
        for (int i = 0; i < 5; ++i) acc[r][i] = 0.f;

    const float4* x4 = (const float4*)x;

    for (int kc = 0; kc < D_IN; kc += 64) {
#pragma unroll
        for (int it = 0; it < 4; ++it) {
            int idx = tid + it * 256;
            int row = idx >> 4;
            int c4  = idx & 15;
            float4 v = x4[(size_t)(t0 + row) * (D_IN / 4) + (kc >> 2) + c4];
            *(float4*)&xs[row][c4 * 4] = v;
        }
#pragma unroll
        for (int it = 0; it < 20; ++it) {
            int idx = tid + it * 256;
            int gq  = idx >> 6;
            int kk  = idx & 63;
            ws[gq][kk] = W_ih[gq * D_IN + kc + kk];
        }
        __syncthreads();

#pragma unroll 4
        for (int k = 0; k < 64; ++k) {
            float xv[4], wv[5];
#pragma unroll
            for (int r = 0; r < 4; ++r) xv[r] = xs[rg * 4 + r][k];
#pragma unroll
            for (int i = 0; i < 5; ++i) wv[i] = ws[gg * 5 + i][k];
#pragma unroll
            for (int r = 0; r < 4; ++r)
#pragma unroll
                for (int i = 0; i < 5; ++i)
                    acc[r][i] = fmaf(xv[r], wv[i], acc[r][i]);
        }
        __syncthreads();
    }

#pragma unroll
    for (int r = 0; r < 4; ++r) {
        size_t rowoff = (size_t)(t0 + rg * 4 + r) * 128;
#pragma unroll
        for (int i = 0; i < 5; ++i) {
            int gate = gg * 5 + i;   // q*20+u
            int q    = gate / HID;
            int u    = gate % HID;
            float val = (acc[r][i] + b_ih[gate] + b_hh[gate]) *
                        ((q == 2) ? 1.f : 0.5f);
            if (q < 3) {
                g_xgp[rowoff + u * 4 + q] = val;
            } else {
                if (u < 12) g_xgp[rowoff + (20 + u) * 4 + 0] = val;
                if (u >= 8) g_xgp[rowoff + (12 + u) * 4 + 1] = val;
            }
        }
    }
}

// ---------------------------------------------------------------------------
// Kernel B: single-warp scan, NO shared memory, NO barriers.
//   h distributed as register pairs via 20 SHFL + 10 packs each step;
//   shfl is warp-synchronizing, h->first-operand latency = 1 shfl (26cy).
//   lane l<20: slot0=i_l, slot1=f_l, slot2=g_l  (c-update needs NO shuffles)
//   lane l>=20: slot0=o_{l-20}, slot1=o_{l-12}, slot2=dummy(0)
// ---------------------------------------------------------------------------
__global__ void __launch_bounds__(32, 1)
lstm_scan_kernel(const float* __restrict__ h_state,
                 const float* __restrict__ c_state,
                 const float* __restrict__ W_hh,
                 float* __restrict__ out) {
    const int l = threadIdx.x;
    const unsigned FULLM = 0xffffffffu;

    const int G0 = (l < 20) ? l        : (40 + l);   // i_l  | o_{l-20}
    const int G1 = (l < 20) ? (20 + l) : (48 + l);   // f_l  | o_{l-12}
    const int G2 = (l < 20) ? (40 + l) : 0;          // g_l  | dummy
    const float s2 = (l < 20) ? 1.f : 0.f;

    // k-paired W_hh rows, sigma rows prescaled x0.5 (tanh row x1)
    ull w0[10], w1[10], w2[10];
#pragma unroll
    for (int m = 0; m < 10; ++m) {
        w0[m] = pack2(0.5f * W_hh[G0 * HID + 2 * m], 0.5f * W_hh[G0 * HID + 2 * m + 1]);
        w1[m] = pack2(0.5f * W_hh[G1 * HID + 2 * m], 0.5f * W_hh[G1 * HID + 2 * m + 1]);
        w2[m] = pack2(s2   * W_hh[G2 * HID + 2 * m], s2   * W_hh[G2 * HID + 2 * m + 1]);
    }

    float c = c_state[(l < HID) ? l : 0];
    float h = (l < HID) ? h_state[l] : 0.f;

    // initial distribution of h pairs (shfl sources are lanes 0..19 only)
    ull hr[10];
#pragma unroll
    for (int m = 0; m < 10; ++m)
        hr[m] = pack2(__shfl_sync(FULLM, h, 2 * m),
                      __shfl_sync(FULLM, h, 2 * m + 1));

    const float4* xq = (const float4*)g_xgp;   // row stride: 32 float4

    float4 ring[4];
#pragma unroll
    for (int i = 0; i < 4; ++i) ring[i] = __ldg(&xq[(size_t)i * 32 + l]);

#define STEP(P, COMP) {                                                      \
    float4 xv = ring[P];                                                     \
    int tp = t + (P) + 4; if (tp > T_LEN - 1) tp = T_LEN - 1;                \
    ring[P] = __ldg(&xq[(size_t)tp * 32 + l]);                               \
    ull a0 = pack2(xv.x, 0.f);                                               \
    ull b0 = pack2(xv.y, 0.f);                                               \
    ull d0 = pack2(xv.z, 0.f);                                               \
    ffma2(a0, w0[0], hr[0]); ffma2(b0, w1[0], hr[0]); ffma2(d0, w2[0], hr[0]); \
    ull a1 = mul2(w0[1], hr[1]);                                             \
    ull b1 = mul2(w1[1], hr[1]);                                             \
    ull d1 = mul2(w2[1], hr[1]);                                             \
    _Pragma("unroll")                                                        \
    for (int m = 2; m < 10; m += 2) {                                        \
        ffma2(a0, w0[m], hr[m]); ffma2(a1, w0[m + 1], hr[m + 1]);            \
        ffma2(b0, w1[m], hr[m]); ffma2(b1, w1[m + 1], hr[m + 1]);            \
        ffma2(d0, w2[m], hr[m]); ffma2(d1, w2[m + 1], hr[m + 1]);            \
    }                                                                        \
    float lo, hi, pre0, pre1, pre2;                                          \
    unpack2(fadd2(a0, a1), lo, hi); pre0 = lo + hi;                          \
    unpack2(fadd2(b0, b1), lo, hi); pre1 = lo + hi;                          \
    unpack2(fadd2(d0, d1), lo, hi); pre2 = lo + hi;                          \
    float i_a = fmaf(0.5f, tanh_mufu(pre0), 0.5f);                           \
    float f_a = fmaf(0.5f, tanh_mufu(pre1), 0.5f);                           \
    float g_a = tanh_mufu(pre2);                                             \
    float oA = __shfl_sync(FULLM, i_a, l + 20);                              \
    float oB = __shfl_sync(FULLM, f_a, l + 12);                              \
    c = fmaf(f_a, c, i_a * g_a);                                             \
    float tc = tanh_mufu(c);                                                 \
    float ov = (l < 12) ? oA : oB;                                           \
    h = ov * tc;                                                             \
    hr[0] = pack2(__shfl_sync(FULLM, h, 0),  __shfl_sync(FULLM, h, 1));      \
    hr[1] = pack2(__shfl_sync(FULLM, h, 2),  __shfl_sync(FULLM, h, 3));      \
    hr[2] = pack2(__shfl_sync(FULLM, h, 4),  __shfl_sync(FULLM, h, 5));      \
    hr[3] = pack2(__shfl_sync(FULLM, h, 6),  __shfl_sync(FULLM, h, 7));      \
    hr[4] = pack2(__shfl_sync(FULLM, h, 8),  __shfl_sync(FULLM, h, 9));      \
    hr[5] = pack2(__shfl_sync(FULLM, h, 10), __shfl_sync(FULLM, h, 11));     \
    hr[6] = pack2(__shfl_sync(FULLM, h, 12), __shfl_sync(FULLM, h, 13));     \
    hr[7] = pack2(__shfl_sync(FULLM, h, 14), __shfl_sync(FULLM, h, 15));     \
    hr[8] = pack2(__shfl_sync(FULLM, h, 16), __shfl_sync(FULLM, h, 17));     \
    hr[9] = pack2(__shfl_sync(FULLM, h, 18), __shfl_sync(FULLM, h, 19));     \
    COMP = h; }

    for (int t = 0; t < T_LEN; t += 4) {
        float4 hb;
        STEP(0, hb.x)
        STEP(1, hb.y)
        STEP(2, hb.z)
        STEP(3, hb.w)
        *(float4*)(g_hT + (size_t)l * T_LEN + t) = hb;   // branchless, 32 rows
    }
#undef STEP

    if (l < HID) {
        out[T_LEN + l]       = h;
        out[T_LEN + HID + l] = c;
    }
}

// ---------------------------------------------------------------------------
// Kernel C: y[t] = sum_u g_hT[u][t] * W_out[u] + b_out
// ---------------------------------------------------------------------------
__global__ void out_proj_kernel(const float* __restrict__ W_out,
                                const float* __restrict__ b_out,
                                float* __restrict__ out) {
    __shared__ float w[HID];
    __shared__ float b0;
    if (threadIdx.x < HID) w[threadIdx.x] = W_out[threadIdx.x];
    if (threadIdx.x == 0)  b0 = b_out[0];
    __syncthreads();

    int t = blockIdx.x * blockDim.x + threadIdx.x;
    if (t < T_LEN) {
        float acc = 0.f;
#pragma unroll
        for (int uu = 0; uu < HID; ++uu)
            acc = fmaf(g_hT[(size_t)uu * T_LEN + t], w[uu], acc);
        out[t] = acc + b0;
    }
}

// ---------------------------------------------------------------------------
extern "C" void kernel_launch(void* const* d_in, const int* in_sizes, int n_in,
                              void* d_out, int out_size) {
    const float* x       = (const float*)d_in[0];
    const float* h_state = (const float*)d_in[1];
    const float* c_state = (const float*)d_in[2];
    const float* W_ih    = (const float*)d_in[3];
    const float* W_hh    = (const float*)d_in[4];
    const float* b_ih    = (const float*)d_in[5];
    const float* b_hh    = (const float*)d_in[6];
    const float* W_out   = (const float*)d_in[7];
    const float* b_out   = (const float*)d_in[8];
    float* out = (float*)d_out;

    gemm_xg_kernel<<<T_LEN / 64, 256>>>(x, W_ih, b_ih, b_hh);
    lstm_scan_kernel<<<1, 32>>>(h_state, c_state, W_hh, out);
    out_proj_kernel<<<(T_LEN + 255) / 256, 256>>>(W_out, b_out, out);
}

// round 9
// speedup vs baseline: 1.1012x; 1.1012x over previous
#include <cuda_runtime.h>

#define T_LEN 32768
#define D_IN  512
#define HID   20
#define G4    80   // 4*HID

// Scratch (static device arrays; no allocation)
// g_xgp: [t][128], col = lane*4 + slot. Lane l<20: slots {i_l,f_l,g_l,pad}.
// Lane l>=20: slots {o_{l-20}, o_{l-12}, 0, pad}. sigma-gates prescaled x0.5.
__device__ float g_xgp[(size_t)T_LEN * 128];
// g_hT: transposed hidden states [lane][t] (32 rows; only 0..19 meaningful)
__device__ float g_hT[(size_t)32 * T_LEN];

typedef unsigned long long ull;

__device__ __forceinline__ ull pack2(float lo, float hi) {
    ull r;
    asm("mov.b64 %0, {%1, %2};" : "=l"(r) : "f"(lo), "f"(hi));
    return r;
}
__device__ __forceinline__ void unpack2(ull v, float& lo, float& hi) {
    asm("mov.b64 {%0, %1}, %2;" : "=f"(lo), "=f"(hi) : "l"(v));
}
__device__ __forceinline__ void ffma2(ull& acc, ull a, ull b) {
    asm("fma.rn.f32x2 %0, %1, %2, %0;" : "+l"(acc) : "l"(a), "l"(b));
}
__device__ __forceinline__ ull fadd2(ull a, ull b) {
    ull r;
    asm("add.rn.f32x2 %0, %1, %2;" : "=l"(r) : "l"(a), "l"(b));
    return r;
}
__device__ __forceinline__ ull mul2(ull a, ull b) {
    ull r;
    asm("mul.rn.f32x2 %0, %1, %2;" : "=l"(r) : "l"(a), "l"(b));
    return r;
}
__device__ __forceinline__ float tanh_mufu(float x) {
    float r;
    asm("tanh.approx.f32 %0, %1;" : "=f"(r) : "f"(x));
    return r;
}

// sync-free same-warp smem exchange (correctness validated in R7):
// STS then LDS in program order; same-warp LSU wavefronts are processed
// in order, so the loads see the stores without a barrier.
__device__ __forceinline__ void sts_h(unsigned addr, float v) {
    asm volatile("st.shared.b32 [%0], %1;" :: "r"(addr), "f"(v) : "memory");
}
__device__ __forceinline__ void lds_pair2(unsigned addr, ull& a, ull& b) {
    asm volatile("ld.shared.v2.u64 {%0, %1}, [%2];"
                 : "=l"(a), "=l"(b) : "r"(addr) : "memory");
}

// ---------------------------------------------------------------------------
// Kernel A: gemm + scatter into the per-lane packed layout. (unchanged)
// ---------------------------------------------------------------------------
__global__ void gemm_xg_kernel(const float* __restrict__ x,
                               const float* __restrict__ W_ih,
                               const float* __restrict__ b_ih,
                               const float* __restrict__ b_hh) {
    __shared__ float xs[64][64];
    __shared__ float ws[80][65];

    const int tid = threadIdx.x;
    const int t0  = blockIdx.x * 64;
    const int rg  = tid >> 4;
    const int gg  = tid & 15;

    // zero unused columns: pad col lane*4+3 (32) + upper-lane slot2 (12)
    for (int idx = tid; idx < 64 * 44; idx += 256) {
        int row = idx / 44;
        int k   = idx % 44;
        int col = (k < 32) ? (k * 4 + 3) : ((20 + (k - 32)) * 4 + 2);
        g_xgp[(size_t)(t0 + row) * 128 + col] = 0.f;
    }

    float acc[4][5];
#pragma unroll
    for (int r = 0; r < 4; ++r)
#pragma unroll
        for (int i = 0; i < 5; ++i) acc[r][i] = 0.f;

    const float4* x4 = (const float4*)x;

    for (int kc = 0; kc < D_IN; kc += 64) {
#pragma unroll
        for (int it = 0; it < 4; ++it) {
            int idx = tid + it * 256;
            int row = idx >> 4;
            int c4  = idx & 15;
            float4 v = x4[(size_t)(t0 + row) * (D_IN / 4) + (kc >> 2) + c4];
            *(float4*)&xs[row][c4 * 4] = v;
        }
#pragma unroll
        for (int it = 0; it < 20; ++it) {
            int idx = tid + it * 256;
            int gq  = idx >> 6;
            int kk  = idx & 63;
            ws[gq][kk] = W_ih[gq * D_IN + kc + kk];
        }
        __syncthreads();

#pragma unroll 4
        for (int k = 0; k < 64; ++k) {
            float xv[4], wv[5];
#pragma unroll
            for (int r = 0; r < 4; ++r) xv[r] = xs[rg * 4 + r][k];
#pragma unroll
            for (int i = 0; i < 5; ++i) wv[i] = ws[gg * 5 + i][k];
#pragma unroll
            for (int r = 0; r < 4; ++r)
#pragma unroll
                for (int i = 0; i < 5; ++i)
                    acc[r][i] = fmaf(xv[r], wv[i], acc[r][i]);
        }
        __syncthreads();
    }

#pragma unroll
    for (int r = 0; r < 4; ++r) {
        size_t rowoff = (size_t)(t0 + rg * 4 + r) * 128;
#pragma unroll
        for (int i = 0; i < 5; ++i) {
            int gate = gg * 5 + i;   // q*20+u
            int q    = gate / HID;
            int u    = gate % HID;
            float val = (acc[r][i] + b_ih[gate] + b_hh[gate]) *
                        ((q == 2) ? 1.f : 0.5f);
            if (q < 3) {
                g_xgp[rowoff + u * 4 + q] = val;
            } else {
                if (u < 12) g_xgp[rowoff + (20 + u) * 4 + 0] = val;
                if (u >= 8) g_xgp[rowoff + (12 + u) * 4 + 1] = val;
            }
        }
    }
}

// ---------------------------------------------------------------------------
// Kernel B: single-warp scan, sync-free smem h-exchange.
//   Step: chains (hr preloaded) -> acts -> c/h -> STS h -> LDS next hr
//   (LDS latency hidden by ring prefetch + hT store + loop control).
// ---------------------------------------------------------------------------
__global__ void __launch_bounds__(32, 1)
lstm_scan_kernel(const float* __restrict__ h_state,
                 const float* __restrict__ c_state,
                 const float* __restrict__ W_hh,
                 float* __restrict__ out) {
    __shared__ __align__(16) float hsm[32];

    const int l = threadIdx.x;
    const unsigned FULLM = 0xffffffffu;

    const unsigned hbase = (unsigned)__cvta_generic_to_shared(hsm);
    const unsigned haddr = hbase + l * 4;

    const int G0 = (l < 20) ? l        : (40 + l);   // i_l  | o_{l-20}
    const int G1 = (l < 20) ? (20 + l) : (48 + l);   // f_l  | o_{l-12}
    const int G2 = (l < 20) ? (40 + l) : 0;          // g_l  | dummy
    const float s2 = (l < 20) ? 1.f : 0.f;

    // k-paired W_hh rows, sigma rows prescaled x0.5 (tanh row x1)
    ull w0[10], w1[10], w2[10];
#pragma unroll
    for (int m = 0; m < 10; ++m) {
        w0[m] = pack2(0.5f * W_hh[G0 * HID + 2 * m], 0.5f * W_hh[G0 * HID + 2 * m + 1]);
        w1[m] = pack2(0.5f * W_hh[G1 * HID + 2 * m], 0.5f * W_hh[G1 * HID + 2 * m + 1]);
        w2[m] = pack2(s2   * W_hh[G2 * HID + 2 * m], s2   * W_hh[G2 * HID + 2 * m + 1]);
    }

    float c = c_state[(l < HID) ? l : 0];
    float h = (l < HID) ? h_state[l] : 0.f;

    ull hr[10];
    sts_h(haddr, h);
    lds_pair2(hbase +  0, hr[0], hr[1]);
    lds_pair2(hbase + 16, hr[2], hr[3]);
    lds_pair2(hbase + 32, hr[4], hr[5]);
    lds_pair2(hbase + 48, hr[6], hr[7]);
    lds_pair2(hbase + 64, hr[8], hr[9]);

    const float4* xq = (const float4*)g_xgp;   // row stride: 32 float4

    float4 ring[4];
#pragma unroll
    for (int i = 0; i < 4; ++i) ring[i] = __ldg(&xq[(size_t)i * 32 + l]);

#define STEP(P, COMP) {                                                      \
    float4 xv = ring[P];                                                     \
    ull a0 = pack2(xv.x, 0.f);                                               \
    ull b0 = pack2(xv.y, 0.f);                                               \
    ull d0 = pack2(xv.z, 0.f);                                               \
    ffma2(a0, w0[0], hr[0]); ffma2(b0, w1[0], hr[0]); ffma2(d0, w2[0], hr[0]); \
    ull a1 = mul2(w0[1], hr[1]);                                             \
    ull b1 = mul2(w1[1], hr[1]);                                             \
    ull d1 = mul2(w2[1], hr[1]);                                             \
    _Pragma("unroll")                                                        \
    for (int m = 2; m < 10; m += 2) {                                        \
        ffma2(a0, w0[m], hr[m]); ffma2(a1, w0[m + 1], hr[m + 1]);            \
        ffma2(b0, w1[m], hr[m]); ffma2(b1, w1[m + 1], hr[m + 1]);            \
        ffma2(d0, w2[m], hr[m]); ffma2(d1, w2[m + 1], hr[m + 1]);            \
    }                                                                        \
    float lo, hi, pre0, pre1, pre2;                                          \
    unpack2(fadd2(a0, a1), lo, hi); pre0 = lo + hi;                          \
    unpack2(fadd2(b0, b1), lo, hi); pre1 = lo + hi;                          \
    unpack2(fadd2(d0, d1), lo, hi); pre2 = lo + hi;                          \
    float i_a = fmaf(0.5f, tanh_mufu(pre0), 0.5f);                           \
    float f_a = fmaf(0.5f, tanh_mufu(pre1), 0.5f);                           \
    float g_a = tanh_mufu(pre2);                                             \
    float oA = __shfl_sync(FULLM, i_a, l + 20);                              \
    float oB = __shfl_sync(FULLM, f_a, l + 12);                              \
    c = fmaf(f_a, c, i_a * g_a);                                             \
    float tc = tanh_mufu(c);                                                 \
    float ov = (l < 12) ? oA : oB;                                           \
    h = ov * tc;                                                             \
    sts_h(haddr, h);                 /* branchless store, all 32 lanes */    \
    lds_pair2(hbase +  0, hr[0], hr[1]);   /* next step's operands; */       \
    lds_pair2(hbase + 16, hr[2], hr[3]);   /* latency hidden by tail */      \
    lds_pair2(hbase + 32, hr[4], hr[5]);                                     \
    lds_pair2(hbase + 48, hr[6], hr[7]);                                     \
    lds_pair2(hbase + 64, hr[8], hr[9]);                                     \
    int tp = t + (P) + 4; if (tp > T_LEN - 1) tp = T_LEN - 1;                \
    ring[P] = __ldg(&xq[(size_t)tp * 32 + l]);                               \
    COMP = h; }

    for (int t = 0; t < T_LEN; t += 4) {
        float4 hb;
        STEP(0, hb.x)
        STEP(1, hb.y)
        STEP(2, hb.z)
        STEP(3, hb.w)
        *(float4*)(g_hT + (size_t)l * T_LEN + t) = hb;   // branchless, 32 rows
    }
#undef STEP

    if (l < HID) {
        out[T_LEN + l]       = h;
        out[T_LEN + HID + l] = c;
    }
}

// ---------------------------------------------------------------------------
// Kernel C: y[t] = sum_u g_hT[u][t] * W_out[u] + b_out
// ---------------------------------------------------------------------------
__global__ void out_proj_kernel(const float* __restrict__ W_out,
                                const float* __restrict__ b_out,
                                float* __restrict__ out) {
    __shared__ float w[HID];
    __shared__ float b0;
    if (threadIdx.x < HID) w[threadIdx.x] = W_out[threadIdx.x];
    if (threadIdx.x == 0)  b0 = b_out[0];
    __syncthreads();

    int t = blockIdx.x * blockDim.x + threadIdx.x;
    if (t < T_LEN) {
        float acc = 0.f;
#pragma unroll
        for (int uu = 0; uu < HID; ++uu)
            acc = fmaf(g_hT[(size_t)uu * T_LEN + t], w[uu], acc);
        out[t] = acc + b0;
    }
}

// ---------------------------------------------------------------------------
extern "C" void kernel_launch(void* const* d_in, const int* in_sizes, int n_in,
                              void* d_out, int out_size) {
    const float* x       = (const float*)d_in[0];
    const float* h_state = (const float*)d_in[1];
    const float* c_state = (const float*)d_in[2];
    const float* W_ih    = (const float*)d_in[3];
    const float* W_hh    = (const float*)d_in[4];
    const float* b_ih    = (const float*)d_in[5];
    const float* b_hh    = (const float*)d_in[6];
    const float* W_out   = (const float*)d_in[7];
    const float* b_out   = (const float*)d_in[8];
    float* out = (float*)d_out;

    gemm_xg_kernel<<<T_LEN / 64, 256>>>(x, W_ih, b_ih, b_hh);
    lstm_scan_kernel<<<1, 32>>>(h_state, c_state, W_hh, out);
    out_proj_kernel<<<(T_LEN + 255) / 256, 256>>>(W_out, b_out, out);
}